// round 14
// baseline (speedup 1.0000x reference)
#include <cuda_runtime.h>
#include <cuda_fp16.h>
#include <math.h>
#include <stdint.h>

#define BATCH 2
#define CTX   2048
#define DM    1024
#define NH    16
#define HD    64
#define BT    (BATCH*CTX)   // 4096

// ---------------- scratch (device globals; no allocation allowed) ----------
__device__ __half g_Xh[BT * DM];
__device__ __half g_Wh[4 * DM * DM];   // transposed weights [N][K], fp16
__device__ __half g_Qh[BT * DM];
__device__ __half g_Kh[BT * DM];
__device__ __half g_Vh[BT * DM];
__device__ __half g_Ch[BT * DM];

// Q projections pre-scaled by 1/sqrt(64) * log2(e): flash works in exp2 domain
#define QSCALE 0.18033688011112042f

// ---------------- helpers ---------------------------------------------------
__device__ __forceinline__ void mma_f16(float* d, const uint32_t* a, uint32_t b0, uint32_t b1) {
    asm volatile(
        "mma.sync.aligned.m16n8k16.row.col.f32.f16.f16.f32 "
        "{%0,%1,%2,%3}, {%4,%5,%6,%7}, {%8,%9}, {%0,%1,%2,%3};"
        : "+f"(d[0]), "+f"(d[1]), "+f"(d[2]), "+f"(d[3])
        : "r"(a[0]), "r"(a[1]), "r"(a[2]), "r"(a[3]), "r"(b0), "r"(b1));
}

__device__ __forceinline__ void ldm4(uint32_t* r, uint32_t addr) {
    asm volatile("ldmatrix.sync.aligned.m8n8.x4.shared.b16 {%0,%1,%2,%3}, [%4];"
                 : "=r"(r[0]), "=r"(r[1]), "=r"(r[2]), "=r"(r[3]) : "r"(addr));
}
__device__ __forceinline__ void ldm4t(uint32_t* r, uint32_t addr) {
    asm volatile("ldmatrix.sync.aligned.m8n8.x4.trans.shared.b16 {%0,%1,%2,%3}, [%4];"
                 : "=r"(r[0]), "=r"(r[1]), "=r"(r[2]), "=r"(r[3]) : "r"(addr));
}

__device__ __forceinline__ void cp16s(uint32_t dst, const void* g) {
    asm volatile("cp.async.ca.shared.global [%0], [%1], 16;" :: "r"(dst), "l"(g));
}
__device__ __forceinline__ void cp_commit() {
    asm volatile("cp.async.commit_group;" ::: "memory");
}
__device__ __forceinline__ uint32_t packh2(float x, float y) {
    __half2 h = __floats2half2_rn(x, y);
    return *(uint32_t*)&h;
}
__device__ __forceinline__ float ex2(float x) {
    float y; asm("ex2.approx.f32 %0, %1;" : "=f"(y) : "f"(x)); return y;
}

// ---------------- fused converter --------------------------------------------
__global__ void conv_all(
    const float* __restrict__ wq, const float* __restrict__ wk,
    const float* __restrict__ wv, const float* __restrict__ wo,
    __half* __restrict__ wh,
    const float4* __restrict__ x, __half2* __restrict__ xh)
{
    const int z = blockIdx.z;
    if (z < 4) {
        __shared__ float tle[32][33];
        const float* in = (z == 0) ? wq : (z == 1) ? wk : (z == 2) ? wv : wo;
        __half* o = wh + (size_t)z * DM * DM;
        int bx = blockIdx.x * 32, by = blockIdx.y * 32;
        int tx = threadIdx.x, ty = threadIdx.y;
        #pragma unroll
        for (int i = 0; i < 4; i++)
            tle[ty + 8 * i][tx] = in[(size_t)(by + ty + 8 * i) * DM + bx + tx];
        __syncthreads();
        #pragma unroll
        for (int i = 0; i < 4; i++)
            o[(size_t)(bx + ty + 8 * i) * DM + by + tx] =
                __float2half_rn(tle[tx][ty + 8 * i]);
    } else {
        int tid = threadIdx.y * 32 + threadIdx.x;
        int i = (((z - 4) * 1024 + blockIdx.y * 32 + blockIdx.x) << 8) + tid;
        float4 v = x[i];
        xh[2 * i]     = __floats2half2_rn(v.x, v.y);
        xh[2 * i + 1] = __floats2half2_rn(v.z, v.w);
    }
}

// ============================================================================
// fp16 GEMM core (unchanged, R13 best). BM=BN=128, BK=32, 4-stage cp.async,
// ONE sync per k-tile. 4 warps (2m x 2n), warp tile 64x64, B frags pipelined.
// ============================================================================
#define G_LD   40
#define G_STG  (128 * G_LD)
#define G_NSTG 4
#define G_SMEM (G_NSTG * 2 * G_STG * 2)    // 81920 B

struct GemmAcc { float a[4][8][4]; };

__device__ __forceinline__ void gemm_core(
    const __half* __restrict__ A, const __half* __restrict__ Bt,
    int row0, int col0, GemmAcc& acc, __half* gsm)
{
    const int tid = threadIdx.x;
    const int lane = tid & 31, wid = tid >> 5;
    const int wm = wid & 1, wn = wid >> 1;

    uint32_t sA = (uint32_t)__cvta_generic_to_shared(gsm);
    uint32_t sB = sA + G_NSTG * G_STG * 2;

    const int a_row = (lane & 7) + ((lane >> 3) & 1) * 8;
    const int a_kof = ((lane >> 4) & 1) * 8;
    const int b_row = (lane & 7) + ((lane >> 4) & 1) * 8;
    const int b_kof = ((lane >> 3) & 1) * 8;

    #pragma unroll
    for (int mt = 0; mt < 4; mt++)
        #pragma unroll
        for (int nt = 0; nt < 8; nt++)
            #pragma unroll
            for (int r = 0; r < 4; r++) acc.a[mt][nt][r] = 0.f;

    const int NT = DM / 32;   // 32
    auto issue = [&](int t) {
        if (t < NT) {
            int buf = t % G_NSTG, k0 = t * 32;
            #pragma unroll
            for (int i = 0; i < 4; i++) {
                int idx = tid + i * 128;
                int r = idx >> 2, c = idx & 3;
                uint32_t off = (uint32_t)(buf * G_STG + r * G_LD + c * 8) * 2;
                cp16s(sA + off, A  + (size_t)(row0 + r) * DM + k0 + c * 8);
                cp16s(sB + off, Bt + (size_t)(col0 + r) * DM + k0 + c * 8);
            }
        }
        cp_commit();
    };

    issue(0); issue(1); issue(2);

    for (int it = 0; it < NT; ++it) {
        asm volatile("cp.async.wait_group 2;" ::: "memory");
        __syncthreads();
        issue(it + 3);

        uint32_t ab = sA + (uint32_t)((it % G_NSTG) * G_STG) * 2;
        uint32_t bb = sB + (uint32_t)((it % G_NSTG) * G_STG) * 2;

        uint32_t a[2][4][4];
        #pragma unroll
        for (int ks = 0; ks < 2; ks++)
            #pragma unroll
            for (int mt = 0; mt < 4; mt++)
                ldm4(a[ks][mt], ab + (uint32_t)((wm * 64 + mt * 16 + a_row) * G_LD
                                                + ks * 16 + a_kof) * 2);

        uint32_t bf[2][4];
        ldm4(bf[0], bb + (uint32_t)((wn * 64 + b_row) * G_LD + b_kof) * 2);
        #pragma unroll
        for (int i = 0; i < 8; i++) {
            int ks = i >> 2, ntp = i & 3;
            if (i + 1 < 8) {
                int nks = (i + 1) >> 2, nntp = (i + 1) & 3;
                ldm4(bf[(i + 1) & 1],
                     bb + (uint32_t)((wn * 64 + nntp * 16 + b_row) * G_LD
                                     + nks * 16 + b_kof) * 2);
            }
            const uint32_t* f = bf[i & 1];
            #pragma unroll
            for (int mt = 0; mt < 4; mt++) {
                mma_f16(acc.a[mt][2 * ntp],     a[ks][mt], f[0], f[1]);
                mma_f16(acc.a[mt][2 * ntp + 1], a[ks][mt], f[2], f[3]);
            }
        }
    }
}

__global__ __launch_bounds__(128, 2) void gemm_qkv(
    const __half* __restrict__ A, const __half* __restrict__ W,
    __half* __restrict__ Qh, __half* __restrict__ Kh, __half* __restrict__ Vh)
{
    extern __shared__ __align__(16) __half gsm[];
    const int mat = blockIdx.x >> 3;
    const int col0 = (blockIdx.x & 7) * 128;
    const int row0 = blockIdx.y * 128;
    const __half* Bt = W + (size_t)mat * DM * DM;
    __half* C = (mat == 0) ? Qh : (mat == 1) ? Kh : Vh;
    const float sc = (mat == 0) ? QSCALE : 1.f;

    GemmAcc acc;
    gemm_core(A, Bt, row0, col0, acc, gsm);

    const int lane = threadIdx.x & 31, wid = threadIdx.x >> 5;
    const int lr = lane >> 2, lc = lane & 3;
    const int wm = wid & 1, wn = wid >> 1;
    #pragma unroll
    for (int mt = 0; mt < 4; mt++) {
        int r = row0 + wm * 64 + mt * 16 + lr;
        #pragma unroll
        for (int nt = 0; nt < 8; nt++) {
            int c = col0 + wn * 64 + nt * 8 + 2 * lc;
            *(__half2*)&C[(size_t)r * DM + c] =
                __floats2half2_rn(acc.a[mt][nt][0] * sc, acc.a[mt][nt][1] * sc);
            *(__half2*)&C[(size_t)(r + 8) * DM + c] =
                __floats2half2_rn(acc.a[mt][nt][2] * sc, acc.a[mt][nt][3] * sc);
        }
    }
}

__global__ __launch_bounds__(128, 2) void gemm_out(
    const __half* __restrict__ A, const __half* __restrict__ Bt,
    const float* __restrict__ bias, float* __restrict__ Cf)
{
    extern __shared__ __align__(16) __half gsm[];
    const int col0 = blockIdx.x * 128, row0 = blockIdx.y * 128;

    GemmAcc acc;
    gemm_core(A, Bt, row0, col0, acc, gsm);

    const int lane = threadIdx.x & 31, wid = threadIdx.x >> 5;
    const int lr = lane >> 2, lc = lane & 3;
    const int wm = wid & 1, wn = wid >> 1;
    #pragma unroll
    for (int mt = 0; mt < 4; mt++) {
        int r = row0 + wm * 64 + mt * 16 + lr;
        #pragma unroll
        for (int nt = 0; nt < 8; nt++) {
            int c = col0 + wn * 64 + nt * 8 + 2 * lc;
            float bx = bias[c], by = bias[c + 1];
            *(float2*)&Cf[(size_t)r * DM + c] =
                make_float2(acc.a[mt][nt][0] + bx, acc.a[mt][nt][1] + by);
            *(float2*)&Cf[(size_t)(r + 8) * DM + c] =
                make_float2(acc.a[mt][nt][2] + bx, acc.a[mt][nt][3] + by);
        }
    }
}

// ============================================================================
// fp16 flash attention (causal, exp2 domain, no max tracking).
// 128 q/CTA, KT=128 keys/pipeline-step (two 64-key halves per step).
// 3 combined KV buffers; Q overlays buffer 2's K-region (dead after hoist).
// 4 warps x 32 q-rows, 2 CTA/SM. ONE sync per 128-key step.
// ============================================================================
#define F_LD   72
#define FB_V   (128 * F_LD)                // V offset within buf (halves)
#define FB_SZ  (2 * 128 * F_LD)            // halves per combined KV buffer
#define F_SMEM (3 * FB_SZ * 2)             // 110592 B

__global__ __launch_bounds__(128, 2) void flash_h(
    const __half* __restrict__ Q, const __half* __restrict__ K,
    const __half* __restrict__ V, __half* __restrict__ O)
{
    extern __shared__ __align__(16) __half fsm[];
    const int tid = threadIdx.x;
    const int lane = tid & 31, wid = tid >> 5;
    const int lr = lane >> 2, lc = lane & 3;
    const int q0 = (gridDim.x - 1 - blockIdx.x) * 128;   // heavy tiles first
    const int h = blockIdx.y, b = blockIdx.z;

    const __half* Qg = Q + (size_t)(b * CTX) * DM + h * HD;
    const __half* Kg = K + (size_t)(b * CTX) * DM + h * HD;
    const __half* Vg = V + (size_t)(b * CTX) * DM + h * HD;

    uint32_t sKV = (uint32_t)__cvta_generic_to_shared(fsm);
    uint32_t sQ  = sKV + (uint32_t)(2 * FB_SZ) * 2;      // buf2 K-region

    const int a_row = (lane & 7) + ((lane >> 3) & 1) * 8;
    const int a_kof = ((lane >> 4) & 1) * 8;
    const int b_row = (lane & 7) + ((lane >> 4) & 1) * 8;
    const int b_kof = ((lane >> 3) & 1) * 8;

    const int nkv = q0 / 128 + 1;   // 128-key tiles

    auto issueKV = [&](int t) {
        if (t < nkv) {
            int kb = t * 128, buf = t % 3;
            #pragma unroll
            for (int i = 0; i < 16; i++) {
                int idx = tid + i * 128;               // 0..2047
                int sel = idx >> 10;                   // 0:K 1:V
                int kk = (idx >> 3) & 127, c = idx & 7;
                const __half* src = (sel ? Vg : Kg) + (size_t)(kb + kk) * DM + c * 8;
                uint32_t dst = sKV +
                    (uint32_t)(buf * FB_SZ + sel * FB_V + kk * F_LD + c * 8) * 2;
                cp16s(dst, src);
            }
        }
        cp_commit();
    };

    // prologue: Q -> buf2 K-region, joins tile-0's commit group
    #pragma unroll
    for (int i = 0; i < 8; i++) {
        int idx = tid + i * 128;
        int q = idx >> 3, c = idx & 7;
        cp16s(sQ + (uint32_t)(q * F_LD + c * 8) * 2, Qg + (size_t)(q0 + q) * DM + c * 8);
    }
    issueKV(0);
    issueKV(1);

    const int qw = wid * 32;
    const int vrow = lane & 15;
    const int vblk = lane >> 4;

    // ---- hoist Q fragments (group 0 = Q + KV0) ----
    asm volatile("cp.async.wait_group 1;" ::: "memory");
    __syncthreads();
    uint32_t qa[4][2][4];
    #pragma unroll
    for (int ks = 0; ks < 4; ks++)
        #pragma unroll
        for (int mt = 0; mt < 2; mt++)
            ldm4(qa[ks][mt], sQ + (uint32_t)((qw + mt * 16 + a_row) * F_LD
                                             + ks * 16 + a_kof) * 2);
    __syncthreads();   // buf2 K-region now reusable (tile 2 writes it in iter 0)

    float l0[2] = {0.f, 0.f}, l1[2] = {0.f, 0.f};
    float o[2][8][4];
    #pragma unroll
    for (int mt = 0; mt < 2; mt++)
        #pragma unroll
        for (int dt = 0; dt < 8; dt++)
            #pragma unroll
            for (int r = 0; r < 4; r++) o[mt][dt][r] = 0.f;

    for (int t = 0; t < nkv; ++t) {
        asm volatile("cp.async.wait_group 1;" ::: "memory");
        __syncthreads();

        uint32_t kbuf = sKV + (uint32_t)((t % 3) * FB_SZ) * 2;
        uint32_t vbuf = kbuf + (uint32_t)FB_V * 2;

        #pragma unroll
        for (int half = 0; half < 2; half++) {
            const int krow0 = half * 64;

            // ---- S = Q @ K^T for this 64-key half ----
            float s[2][8][4];
            #pragma unroll
            for (int mt = 0; mt < 2; mt++)
                #pragma unroll
                for (int nt = 0; nt < 8; nt++)
                    #pragma unroll
                    for (int r = 0; r < 4; r++) s[mt][nt][r] = 0.f;

            {
                uint32_t bf[2][4];
                ldm4(bf[0], kbuf + (uint32_t)((krow0 + b_row) * F_LD + b_kof) * 2);
                #pragma unroll
                for (int i = 0; i < 16; i++) {
                    int ks = i >> 2, ntp = i & 3;
                    if (i + 1 < 16) {
                        int nks = (i + 1) >> 2, nntp = (i + 1) & 3;
                        ldm4(bf[(i + 1) & 1],
                             kbuf + (uint32_t)((krow0 + nntp * 16 + b_row) * F_LD
                                               + nks * 16 + b_kof) * 2);
                    }
                    const uint32_t* f = bf[i & 1];
                    #pragma unroll
                    for (int mt = 0; mt < 2; mt++) {
                        mma_f16(s[mt][2 * ntp],     qa[ks][mt], f[0], f[1]);
                        mma_f16(s[mt][2 * ntp + 1], qa[ks][mt], f[2], f[3]);
                    }
                }
            }

            if (half == 0) issueKV(t + 2);   // buf (t+2)%3 freed by top-of-loop sync

            const int kb = t * 128 + krow0;

            if (kb + 63 > q0) {
                #pragma unroll
                for (int mt = 0; mt < 2; mt++) {
                    int r0 = q0 + qw + mt * 16 + lr, r1 = r0 + 8;
                    #pragma unroll
                    for (int nt = 0; nt < 8; nt++) {
                        #pragma unroll
                        for (int j = 0; j < 2; j++) {
                            int key = kb + nt * 8 + 2 * lc + j;
                            if (key > r0) s[mt][nt][j]     = -1e30f;
                            if (key > r1) s[mt][nt][2 + j] = -1e30f;
                        }
                    }
                }
            }

            // ---- P = exp2(S); l += sum(P) ----
            #pragma unroll
            for (int mt = 0; mt < 2; mt++) {
                #pragma unroll
                for (int nt = 0; nt < 8; nt++) {
                    s[mt][nt][0] = ex2(s[mt][nt][0]);
                    s[mt][nt][1] = ex2(s[mt][nt][1]);
                    s[mt][nt][2] = ex2(s[mt][nt][2]);
                    s[mt][nt][3] = ex2(s[mt][nt][3]);
                    l0[mt] += s[mt][nt][0] + s[mt][nt][1];
                    l1[mt] += s[mt][nt][2] + s[mt][nt][3];
                }
            }

            // ---- pack P fragments ----
            uint32_t pa[4][2][4];
            #pragma unroll
            for (int ks = 0; ks < 4; ks++)
                #pragma unroll
                for (int mt = 0; mt < 2; mt++) {
                    pa[ks][mt][0] = packh2(s[mt][2 * ks][0],     s[mt][2 * ks][1]);
                    pa[ks][mt][1] = packh2(s[mt][2 * ks][2],     s[mt][2 * ks][3]);
                    pa[ks][mt][2] = packh2(s[mt][2 * ks + 1][0], s[mt][2 * ks + 1][1]);
                    pa[ks][mt][3] = packh2(s[mt][2 * ks + 1][2], s[mt][2 * ks + 1][3]);
                }

            // ---- O += P @ V for this half ----
            {
                uint32_t vb[2][4];
                ldm4t(vb[0], vbuf + (uint32_t)((krow0 + vrow) * F_LD + vblk * 8) * 2);
                #pragma unroll
                for (int i = 0; i < 16; i++) {
                    int ks = i >> 2, ntp = i & 3;
                    if (i + 1 < 16) {
                        int nks = (i + 1) >> 2, nntp = (i + 1) & 3;
                        ldm4t(vb[(i + 1) & 1],
                              vbuf + (uint32_t)((krow0 + nks * 16 + vrow) * F_LD
                                                + (2 * nntp + vblk) * 8) * 2);
                    }
                    const uint32_t* f = vb[i & 1];
                    #pragma unroll
                    for (int mt = 0; mt < 2; mt++) {
                        mma_f16(o[mt][2 * ntp],     pa[ks][mt], f[0], f[1]);
                        mma_f16(o[mt][2 * ntp + 1], pa[ks][mt], f[2], f[3]);
                    }
                }
            }
        }
    }

    // ---- epilogue: reduce l across the quad, normalize, write ----
    __half* Og = O + (size_t)(b * CTX) * DM + h * HD;
    #pragma unroll
    for (int mt = 0; mt < 2; mt++) {
        float r0sum = l0[mt], r1sum = l1[mt];
        r0sum += __shfl_xor_sync(0xffffffffu, r0sum, 1);
        r0sum += __shfl_xor_sync(0xffffffffu, r0sum, 2);
        r1sum += __shfl_xor_sync(0xffffffffu, r1sum, 1);
        r1sum += __shfl_xor_sync(0xffffffffu, r1sum, 2);
        float i0 = 1.f / r0sum, i1 = 1.f / r1sum;
        int r0 = q0 + qw + mt * 16 + lr;
        #pragma unroll
        for (int dt = 0; dt < 8; dt++) {
            int c = dt * 8 + 2 * lc;
            *(__half2*)&Og[(size_t)r0 * DM + c] =
                __floats2half2_rn(o[mt][dt][0] * i0, o[mt][dt][1] * i0);
            *(__half2*)&Og[(size_t)(r0 + 8) * DM + c] =
                __floats2half2_rn(o[mt][dt][2] * i1, o[mt][dt][3] * i1);
        }
    }
}

// ============================================================================
// launch
// ============================================================================
extern "C" void kernel_launch(void* const* d_in, const int* in_sizes, int n_in,
                              void* d_out, int out_size)
{
    const float* x  = (const float*)d_in[0];
    const float* Wq = (const float*)d_in[1];
    const float* Wk = (const float*)d_in[2];
    const float* Wv = (const float*)d_in[3];
    const float* Wo = (const float*)d_in[4];
    const float* bo = (const float*)d_in[5];
    float* out = (float*)d_out;

    __half *Xh, *Wh, *Qh, *Kh, *Vh, *Ch;
    cudaGetSymbolAddress((void**)&Xh, g_Xh);
    cudaGetSymbolAddress((void**)&Wh, g_Wh);
    cudaGetSymbolAddress((void**)&Qh, g_Qh);
    cudaGetSymbolAddress((void**)&Kh, g_Kh);
    cudaGetSymbolAddress((void**)&Vh, g_Vh);
    cudaGetSymbolAddress((void**)&Ch, g_Ch);

    cudaFuncSetAttribute(gemm_qkv, cudaFuncAttributeMaxDynamicSharedMemorySize, G_SMEM);
    cudaFuncSetAttribute(gemm_out, cudaFuncAttributeMaxDynamicSharedMemorySize, G_SMEM);
    cudaFuncSetAttribute(flash_h, cudaFuncAttributeMaxDynamicSharedMemorySize, F_SMEM);

    // fused converters: weights (z<4) + x (z>=4)
    dim3 cgrid(32, 32, 8), cblk(32, 8);
    conv_all<<<cgrid, cblk>>>(Wq, Wk, Wv, Wo, Wh, (const float4*)x, (__half2*)Xh);

    dim3 qgrid(24, BT / 128);          // fused QKV
    gemm_qkv<<<qgrid, 128, G_SMEM>>>(Xh, Wh, Qh, Kh, Vh);

    dim3 fgrid(CTX / 128, NH, BATCH);  // (16, 16, 2)
    flash_h<<<fgrid, 128, F_SMEM>>>(Qh, Kh, Vh, Ch);

    dim3 ogrid(DM / 128, BT / 128);
    gemm_out<<<ogrid, 128, G_SMEM>>>(Ch, Wh + 3 * (size_t)DM * DM, bo, out);
}

// round 15
// speedup vs baseline: 1.0139x; 1.0139x over previous
#include <cuda_runtime.h>
#include <cuda_fp16.h>
#include <math.h>
#include <stdint.h>

#define BATCH 2
#define CTX   2048
#define DM    1024
#define NH    16
#define HD    64
#define BT    (BATCH*CTX)   // 4096

// ---------------- scratch (device globals; no allocation allowed) ----------
__device__ __half g_Xh[BT * DM];
__device__ __half g_Wh[4 * DM * DM];   // transposed weights [N][K], fp16
__device__ __half g_Qh[BT * DM];
__device__ __half g_Kh[BT * DM];
__device__ __half g_Vh[BT * DM];
__device__ __half g_Ch[BT * DM];

// Q projections pre-scaled by 1/sqrt(64) * log2(e): flash works in exp2 domain
#define QSCALE 0.18033688011112042f

// ---------------- helpers ---------------------------------------------------
__device__ __forceinline__ void mma_f16(float* d, const uint32_t* a, uint32_t b0, uint32_t b1) {
    asm volatile(
        "mma.sync.aligned.m16n8k16.row.col.f32.f16.f16.f32 "
        "{%0,%1,%2,%3}, {%4,%5,%6,%7}, {%8,%9}, {%0,%1,%2,%3};"
        : "+f"(d[0]), "+f"(d[1]), "+f"(d[2]), "+f"(d[3])
        : "r"(a[0]), "r"(a[1]), "r"(a[2]), "r"(a[3]), "r"(b0), "r"(b1));
}

__device__ __forceinline__ void ldm4(uint32_t* r, uint32_t addr) {
    asm volatile("ldmatrix.sync.aligned.m8n8.x4.shared.b16 {%0,%1,%2,%3}, [%4];"
                 : "=r"(r[0]), "=r"(r[1]), "=r"(r[2]), "=r"(r[3]) : "r"(addr));
}
__device__ __forceinline__ void ldm4t(uint32_t* r, uint32_t addr) {
    asm volatile("ldmatrix.sync.aligned.m8n8.x4.trans.shared.b16 {%0,%1,%2,%3}, [%4];"
                 : "=r"(r[0]), "=r"(r[1]), "=r"(r[2]), "=r"(r[3]) : "r"(addr));
}

// L2-only caching: keep inbound fills out of the contended L1 path
__device__ __forceinline__ void cp16s(uint32_t dst, const void* g) {
    asm volatile("cp.async.cg.shared.global [%0], [%1], 16;" :: "r"(dst), "l"(g));
}
__device__ __forceinline__ void cp_commit() {
    asm volatile("cp.async.commit_group;" ::: "memory");
}
__device__ __forceinline__ uint32_t packh2(float x, float y) {
    __half2 h = __floats2half2_rn(x, y);
    return *(uint32_t*)&h;
}
__device__ __forceinline__ float ex2(float x) {
    float y; asm("ex2.approx.f32 %0, %1;" : "=f"(y) : "f"(x)); return y;
}

// ---------------- fused converter --------------------------------------------
__global__ void conv_all(
    const float* __restrict__ wq, const float* __restrict__ wk,
    const float* __restrict__ wv, const float* __restrict__ wo,
    __half* __restrict__ wh,
    const float4* __restrict__ x, __half2* __restrict__ xh)
{
    const int z = blockIdx.z;
    if (z < 4) {
        __shared__ float tle[32][33];
        const float* in = (z == 0) ? wq : (z == 1) ? wk : (z == 2) ? wv : wo;
        __half* o = wh + (size_t)z * DM * DM;
        int bx = blockIdx.x * 32, by = blockIdx.y * 32;
        int tx = threadIdx.x, ty = threadIdx.y;
        #pragma unroll
        for (int i = 0; i < 4; i++)
            tle[ty + 8 * i][tx] = in[(size_t)(by + ty + 8 * i) * DM + bx + tx];
        __syncthreads();
        #pragma unroll
        for (int i = 0; i < 4; i++)
            o[(size_t)(bx + ty + 8 * i) * DM + by + tx] =
                __float2half_rn(tle[tx][ty + 8 * i]);
    } else {
        int tid = threadIdx.y * 32 + threadIdx.x;
        int i = (((z - 4) * 1024 + blockIdx.y * 32 + blockIdx.x) << 8) + tid;
        float4 v = x[i];
        xh[2 * i]     = __floats2half2_rn(v.x, v.y);
        xh[2 * i + 1] = __floats2half2_rn(v.z, v.w);
    }
}

// ============================================================================
// fp16 GEMM core. BM=BN=128, BK=32, 4-stage cp.async, ONE sync per k-tile.
// 4 warps (2m x 2n), warp tile 64x64, B fragments register-double-buffered.
// ============================================================================
#define G_LD   40
#define G_STG  (128 * G_LD)
#define G_NSTG 4
#define G_SMEM (G_NSTG * 2 * G_STG * 2)    // 81920 B

struct GemmAcc { float a[4][8][4]; };

__device__ __forceinline__ void gemm_core(
    const __half* __restrict__ A, const __half* __restrict__ Bt,
    int row0, int col0, GemmAcc& acc, __half* gsm)
{
    const int tid = threadIdx.x;
    const int lane = tid & 31, wid = tid >> 5;
    const int wm = wid & 1, wn = wid >> 1;

    uint32_t sA = (uint32_t)__cvta_generic_to_shared(gsm);
    uint32_t sB = sA + G_NSTG * G_STG * 2;

    const int a_row = (lane & 7) + ((lane >> 3) & 1) * 8;
    const int a_kof = ((lane >> 4) & 1) * 8;
    const int b_row = (lane & 7) + ((lane >> 4) & 1) * 8;
    const int b_kof = ((lane >> 3) & 1) * 8;

    #pragma unroll
    for (int mt = 0; mt < 4; mt++)
        #pragma unroll
        for (int nt = 0; nt < 8; nt++)
            #pragma unroll
            for (int r = 0; r < 4; r++) acc.a[mt][nt][r] = 0.f;

    const int NT = DM / 32;   // 32
    auto issue = [&](int t) {
        if (t < NT) {
            int buf = t % G_NSTG, k0 = t * 32;
            #pragma unroll
            for (int i = 0; i < 4; i++) {
                int idx = tid + i * 128;
                int r = idx >> 2, c = idx & 3;
                uint32_t off = (uint32_t)(buf * G_STG + r * G_LD + c * 8) * 2;
                cp16s(sA + off, A  + (size_t)(row0 + r) * DM + k0 + c * 8);
                cp16s(sB + off, Bt + (size_t)(col0 + r) * DM + k0 + c * 8);
            }
        }
        cp_commit();
    };

    issue(0); issue(1); issue(2);

    for (int it = 0; it < NT; ++it) {
        asm volatile("cp.async.wait_group 2;" ::: "memory");
        __syncthreads();
        issue(it + 3);

        uint32_t ab = sA + (uint32_t)((it % G_NSTG) * G_STG) * 2;
        uint32_t bb = sB + (uint32_t)((it % G_NSTG) * G_STG) * 2;

        uint32_t a[2][4][4];
        #pragma unroll
        for (int ks = 0; ks < 2; ks++)
            #pragma unroll
            for (int mt = 0; mt < 4; mt++)
                ldm4(a[ks][mt], ab + (uint32_t)((wm * 64 + mt * 16 + a_row) * G_LD
                                                + ks * 16 + a_kof) * 2);

        uint32_t bf[2][4];
        ldm4(bf[0], bb + (uint32_t)((wn * 64 + b_row) * G_LD + b_kof) * 2);
        #pragma unroll
        for (int i = 0; i < 8; i++) {
            int ks = i >> 2, ntp = i & 3;
            if (i + 1 < 8) {
                int nks = (i + 1) >> 2, nntp = (i + 1) & 3;
                ldm4(bf[(i + 1) & 1],
                     bb + (uint32_t)((wn * 64 + nntp * 16 + b_row) * G_LD
                                     + nks * 16 + b_kof) * 2);
            }
            const uint32_t* f = bf[i & 1];
            #pragma unroll
            for (int mt = 0; mt < 4; mt++) {
                mma_f16(acc.a[mt][2 * ntp],     a[ks][mt], f[0], f[1]);
                mma_f16(acc.a[mt][2 * ntp + 1], a[ks][mt], f[2], f[3]);
            }
        }
    }
}

// Fused QKV: grid (24, 32). mat = bx>>3 selects weight + destination.
__global__ __launch_bounds__(128, 2) void gemm_qkv(
    const __half* __restrict__ A, const __half* __restrict__ W,
    __half* __restrict__ Qh, __half* __restrict__ Kh, __half* __restrict__ Vh)
{
    extern __shared__ __align__(16) __half gsm[];
    const int mat = blockIdx.x >> 3;
    const int col0 = (blockIdx.x & 7) * 128;
    const int row0 = blockIdx.y * 128;
    const __half* Bt = W + (size_t)mat * DM * DM;
    __half* C = (mat == 0) ? Qh : (mat == 1) ? Kh : Vh;
    const float sc = (mat == 0) ? QSCALE : 1.f;

    GemmAcc acc;
    gemm_core(A, Bt, row0, col0, acc, gsm);

    const int lane = threadIdx.x & 31, wid = threadIdx.x >> 5;
    const int lr = lane >> 2, lc = lane & 3;
    const int wm = wid & 1, wn = wid >> 1;
    #pragma unroll
    for (int mt = 0; mt < 4; mt++) {
        int r = row0 + wm * 64 + mt * 16 + lr;
        #pragma unroll
        for (int nt = 0; nt < 8; nt++) {
            int c = col0 + wn * 64 + nt * 8 + 2 * lc;
            *(__half2*)&C[(size_t)r * DM + c] =
                __floats2half2_rn(acc.a[mt][nt][0] * sc, acc.a[mt][nt][1] * sc);
            *(__half2*)&C[(size_t)(r + 8) * DM + c] =
                __floats2half2_rn(acc.a[mt][nt][2] * sc, acc.a[mt][nt][3] * sc);
        }
    }
}

// Out projection: fp32 output + bias
__global__ __launch_bounds__(128, 2) void gemm_out(
    const __half* __restrict__ A, const __half* __restrict__ Bt,
    const float* __restrict__ bias, float* __restrict__ Cf)
{
    extern __shared__ __align__(16) __half gsm[];
    const int col0 = blockIdx.x * 128, row0 = blockIdx.y * 128;

    GemmAcc acc;
    gemm_core(A, Bt, row0, col0, acc, gsm);

    const int lane = threadIdx.x & 31, wid = threadIdx.x >> 5;
    const int lr = lane >> 2, lc = lane & 3;
    const int wm = wid & 1, wn = wid >> 1;
    #pragma unroll
    for (int mt = 0; mt < 4; mt++) {
        int r = row0 + wm * 64 + mt * 16 + lr;
        #pragma unroll
        for (int nt = 0; nt < 8; nt++) {
            int c = col0 + wn * 64 + nt * 8 + 2 * lc;
            float bx = bias[c], by = bias[c + 1];
            *(float2*)&Cf[(size_t)r * DM + c] =
                make_float2(acc.a[mt][nt][0] + bx, acc.a[mt][nt][1] + by);
            *(float2*)&Cf[(size_t)(r + 8) * DM + c] =
                make_float2(acc.a[mt][nt][2] + bx, acc.a[mt][nt][3] + by);
        }
    }
}

// ============================================================================
// fp16 flash attention (causal, exp2 domain, no max tracking).
// 128 q/CTA, 64 kv/tile, 4 warps x 32 q-rows, 2 CTA/SM.
// Q fragments hoisted; K/V fragments register-double-buffered.
// ============================================================================
#define F_LD   72
#define F_QP   (128 * F_LD)
#define F_KV   (64 * F_LD)
#define F_SMEM ((F_QP + 3 * F_KV + 3 * F_KV) * 2)   // 73728 B

__global__ __launch_bounds__(128, 2) void flash_h(
    const __half* __restrict__ Q, const __half* __restrict__ K,
    const __half* __restrict__ V, __half* __restrict__ O)
{
    extern __shared__ __align__(16) __half fsm[];
    const int tid = threadIdx.x;
    const int lane = tid & 31, wid = tid >> 5;
    const int lr = lane >> 2, lc = lane & 3;
    const int q0 = (gridDim.x - 1 - blockIdx.x) * 128;   // heavy tiles first
    const int h = blockIdx.y, b = blockIdx.z;

    const __half* Qg = Q + (size_t)(b * CTX) * DM + h * HD;
    const __half* Kg = K + (size_t)(b * CTX) * DM + h * HD;
    const __half* Vg = V + (size_t)(b * CTX) * DM + h * HD;

    uint32_t sQ = (uint32_t)__cvta_generic_to_shared(fsm);
    uint32_t sK = sQ + F_QP * 2;
    uint32_t sV = sK + 3 * F_KV * 2;

    const int a_row = (lane & 7) + ((lane >> 3) & 1) * 8;
    const int a_kof = ((lane >> 4) & 1) * 8;
    const int b_row = (lane & 7) + ((lane >> 4) & 1) * 8;
    const int b_kof = ((lane >> 3) & 1) * 8;

    const int nkv = q0 / 64 + 2;

    auto issueKV = [&](int t) {
        if (t < nkv) {
            int kb = t * 64, buf = t % 3;
            #pragma unroll
            for (int i = 0; i < 8; i++) {
                int idx = tid + i * 128;
                int sel = idx >> 9;
                int kk = (idx >> 3) & 63, c = idx & 7;
                const __half* src = (sel ? Vg : Kg) + (size_t)(kb + kk) * DM + c * 8;
                uint32_t dst = (sel ? sV : sK) +
                               (uint32_t)(buf * F_KV + kk * F_LD + c * 8) * 2;
                cp16s(dst, src);
            }
        }
        cp_commit();
    };

    // prologue: Q tile joins tile-0's commit group
    #pragma unroll
    for (int i = 0; i < 8; i++) {
        int idx = tid + i * 128;
        int q = idx >> 3, c = idx & 7;
        cp16s(sQ + (uint32_t)(q * F_LD + c * 8) * 2, Qg + (size_t)(q0 + q) * DM + c * 8);
    }
    issueKV(0);
    issueKV(1);

    const int qw = wid * 32;
    const int vrow = lane & 15;
    const int vblk = lane >> 4;

    // ---- hoist Q fragments ----
    asm volatile("cp.async.wait_group 1;" ::: "memory");
    __syncthreads();
    uint32_t qa[4][2][4];
    #pragma unroll
    for (int ks = 0; ks < 4; ks++)
        #pragma unroll
        for (int mt = 0; mt < 2; mt++)
            ldm4(qa[ks][mt], sQ + (uint32_t)((qw + mt * 16 + a_row) * F_LD
                                             + ks * 16 + a_kof) * 2);

    float l0[2] = {0.f, 0.f}, l1[2] = {0.f, 0.f};
    float o[2][8][4];
    #pragma unroll
    for (int mt = 0; mt < 2; mt++)
        #pragma unroll
        for (int dt = 0; dt < 8; dt++)
            #pragma unroll
            for (int r = 0; r < 4; r++) o[mt][dt][r] = 0.f;

    for (int t = 0; t < nkv; ++t) {
        asm volatile("cp.async.wait_group 1;" ::: "memory");
        __syncthreads();

        uint32_t kbuf = sK + (uint32_t)((t % 3) * F_KV) * 2;
        uint32_t vbuf = sV + (uint32_t)((t % 3) * F_KV) * 2;

        // ---- S = Q @ K^T: K fragments pipelined over 16 (ks,ntp) steps ----
        float s[2][8][4];
        #pragma unroll
        for (int mt = 0; mt < 2; mt++)
            #pragma unroll
            for (int nt = 0; nt < 8; nt++)
                #pragma unroll
                for (int r = 0; r < 4; r++) s[mt][nt][r] = 0.f;

        {
            uint32_t bf[2][4];
            ldm4(bf[0], kbuf + (uint32_t)(b_row * F_LD + b_kof) * 2);
            #pragma unroll
            for (int i = 0; i < 16; i++) {
                int ks = i >> 2, ntp = i & 3;
                if (i + 1 < 16) {
                    int nks = (i + 1) >> 2, nntp = (i + 1) & 3;
                    ldm4(bf[(i + 1) & 1],
                         kbuf + (uint32_t)((nntp * 16 + b_row) * F_LD
                                           + nks * 16 + b_kof) * 2);
                }
                const uint32_t* f = bf[i & 1];
                #pragma unroll
                for (int mt = 0; mt < 2; mt++) {
                    mma_f16(s[mt][2 * ntp],     qa[ks][mt], f[0], f[1]);
                    mma_f16(s[mt][2 * ntp + 1], qa[ks][mt], f[2], f[3]);
                }
            }
        }

        issueKV(t + 2);   // buffer consumed at t-1; sync above proves safety

        const int kb = t * 64;

        if (kb + 63 > q0) {
            #pragma unroll
            for (int mt = 0; mt < 2; mt++) {
                int r0 = q0 + qw + mt * 16 + lr, r1 = r0 + 8;
                #pragma unroll
                for (int nt = 0; nt < 8; nt++) {
                    #pragma unroll
                    for (int j = 0; j < 2; j++) {
                        int key = kb + nt * 8 + 2 * lc + j;
                        if (key > r0) s[mt][nt][j]     = -1e30f;
                        if (key > r1) s[mt][nt][2 + j] = -1e30f;
                    }
                }
            }
        }

        // ---- P = exp2(S); l += sum(P) ----
        #pragma unroll
        for (int mt = 0; mt < 2; mt++) {
            #pragma unroll
            for (int nt = 0; nt < 8; nt++) {
                s[mt][nt][0] = ex2(s[mt][nt][0]);
                s[mt][nt][1] = ex2(s[mt][nt][1]);
                s[mt][nt][2] = ex2(s[mt][nt][2]);
                s[mt][nt][3] = ex2(s[mt][nt][3]);
                l0[mt] += s[mt][nt][0] + s[mt][nt][1];
                l1[mt] += s[mt][nt][2] + s[mt][nt][3];
            }
        }

        // ---- pack P fragments (C-frag == A-frag layout) ----
        uint32_t pa[4][2][4];
        #pragma unroll
        for (int ks = 0; ks < 4; ks++)
            #pragma unroll
            for (int mt = 0; mt < 2; mt++) {
                pa[ks][mt][0] = packh2(s[mt][2 * ks][0],     s[mt][2 * ks][1]);
                pa[ks][mt][1] = packh2(s[mt][2 * ks][2],     s[mt][2 * ks][3]);
                pa[ks][mt][2] = packh2(s[mt][2 * ks + 1][0], s[mt][2 * ks + 1][1]);
                pa[ks][mt][3] = packh2(s[mt][2 * ks + 1][2], s[mt][2 * ks + 1][3]);
            }

        // ---- O += P @ V: V fragments pipelined over 16 (ks,ntp) steps ----
        {
            uint32_t vb[2][4];
            ldm4t(vb[0], vbuf + (uint32_t)(vrow * F_LD + vblk * 8) * 2);
            #pragma unroll
            for (int i = 0; i < 16; i++) {
                int ks = i >> 2, ntp = i & 3;
                if (i + 1 < 16) {
                    int nks = (i + 1) >> 2, nntp = (i + 1) & 3;
                    ldm4t(vb[(i + 1) & 1],
                          vbuf + (uint32_t)((nks * 16 + vrow) * F_LD
                                            + (2 * nntp + vblk) * 8) * 2);
                }
                const uint32_t* f = vb[i & 1];
                #pragma unroll
                for (int mt = 0; mt < 2; mt++) {
                    mma_f16(o[mt][2 * ntp],     pa[ks][mt], f[0], f[1]);
                    mma_f16(o[mt][2 * ntp + 1], pa[ks][mt], f[2], f[3]);
                }
            }
        }
    }

    // ---- epilogue: reduce l across the quad (once), normalize, write ----
    __half* Og = O + (size_t)(b * CTX) * DM + h * HD;
    #pragma unroll
    for (int mt = 0; mt < 2; mt++) {
        float r0sum = l0[mt], r1sum = l1[mt];
        r0sum += __shfl_xor_sync(0xffffffffu, r0sum, 1);
        r0sum += __shfl_xor_sync(0xffffffffu, r0sum, 2);
        r1sum += __shfl_xor_sync(0xffffffffu, r1sum, 1);
        r1sum += __shfl_xor_sync(0xffffffffu, r1sum, 2);
        float i0 = 1.f / r0sum, i1 = 1.f / r1sum;
        int r0 = q0 + qw + mt * 16 + lr;
        #pragma unroll
        for (int dt = 0; dt < 8; dt++) {
            int c = dt * 8 + 2 * lc;
            *(__half2*)&Og[(size_t)r0 * DM + c] =
                __floats2half2_rn(o[mt][dt][0] * i0, o[mt][dt][1] * i0);
            *(__half2*)&Og[(size_t)(r0 + 8) * DM + c] =
                __floats2half2_rn(o[mt][dt][2] * i1, o[mt][dt][3] * i1);
        }
    }
}

// ============================================================================
// launch
// ============================================================================
extern "C" void kernel_launch(void* const* d_in, const int* in_sizes, int n_in,
                              void* d_out, int out_size)
{
    const float* x  = (const float*)d_in[0];
    const float* Wq = (const float*)d_in[1];
    const float* Wk = (const float*)d_in[2];
    const float* Wv = (const float*)d_in[3];
    const float* Wo = (const float*)d_in[4];
    const float* bo = (const float*)d_in[5];
    float* out = (float*)d_out;

    __half *Xh, *Wh, *Qh, *Kh, *Vh, *Ch;
    cudaGetSymbolAddress((void**)&Xh, g_Xh);
    cudaGetSymbolAddress((void**)&Wh, g_Wh);
    cudaGetSymbolAddress((void**)&Qh, g_Qh);
    cudaGetSymbolAddress((void**)&Kh, g_Kh);
    cudaGetSymbolAddress((void**)&Vh, g_Vh);
    cudaGetSymbolAddress((void**)&Ch, g_Ch);

    cudaFuncSetAttribute(gemm_qkv, cudaFuncAttributeMaxDynamicSharedMemorySize, G_SMEM);
    cudaFuncSetAttribute(gemm_out, cudaFuncAttributeMaxDynamicSharedMemorySize, G_SMEM);
    cudaFuncSetAttribute(flash_h, cudaFuncAttributeMaxDynamicSharedMemorySize, F_SMEM);

    // fused converters: weights (z<4) + x (z>=4)
    dim3 cgrid(32, 32, 8), cblk(32, 8);
    conv_all<<<cgrid, cblk>>>(Wq, Wk, Wv, Wo, Wh, (const float4*)x, (__half2*)Xh);

    dim3 qgrid(24, BT / 128);          // fused QKV
    gemm_qkv<<<qgrid, 128, G_SMEM>>>(Xh, Wh, Qh, Kh, Vh);

    dim3 fgrid(CTX / 128, NH, BATCH);  // (16, 16, 2)
    flash_h<<<fgrid, 128, F_SMEM>>>(Qh, Kh, Vh, Ch);

    dim3 ogrid(DM / 128, BT / 128);
    gemm_out<<<ogrid, 128, G_SMEM>>>(Ch, Wh + 3 * (size_t)DM * DM, bo, out);
}

// round 16
// speedup vs baseline: 1.0395x; 1.0253x over previous
#include <cuda_runtime.h>
#include <cuda_fp16.h>
#include <math.h>
#include <stdint.h>

#define BATCH 2
#define CTX   2048
#define DM    1024
#define NH    16
#define HD    64
#define BT    (BATCH*CTX)   // 4096

// ---------------- scratch (device globals; no allocation allowed) ----------
__device__ __half g_Xh[BT * DM];
__device__ __half g_Wh[4 * DM * DM];   // transposed weights [N][K], fp16
__device__ __half g_Qh[BT * DM];
__device__ __half g_Kh[BT * DM];
__device__ __half g_Vh[BT * DM];
__device__ __half g_Ch[BT * DM];

// Q projections pre-scaled by 1/sqrt(64) * log2(e): flash works in exp2 domain
#define QSCALE 0.18033688011112042f

// ---------------- helpers ---------------------------------------------------
__device__ __forceinline__ void mma_f16(float* d, const uint32_t* a, uint32_t b0, uint32_t b1) {
    asm volatile(
        "mma.sync.aligned.m16n8k16.row.col.f32.f16.f16.f32 "
        "{%0,%1,%2,%3}, {%4,%5,%6,%7}, {%8,%9}, {%0,%1,%2,%3};"
        : "+f"(d[0]), "+f"(d[1]), "+f"(d[2]), "+f"(d[3])
        : "r"(a[0]), "r"(a[1]), "r"(a[2]), "r"(a[3]), "r"(b0), "r"(b1));
}

__device__ __forceinline__ void ldm4(uint32_t* r, uint32_t addr) {
    asm volatile("ldmatrix.sync.aligned.m8n8.x4.shared.b16 {%0,%1,%2,%3}, [%4];"
                 : "=r"(r[0]), "=r"(r[1]), "=r"(r[2]), "=r"(r[3]) : "r"(addr));
}
__device__ __forceinline__ void ldm4t(uint32_t* r, uint32_t addr) {
    asm volatile("ldmatrix.sync.aligned.m8n8.x4.trans.shared.b16 {%0,%1,%2,%3}, [%4];"
                 : "=r"(r[0]), "=r"(r[1]), "=r"(r[2]), "=r"(r[3]) : "r"(addr));
}

__device__ __forceinline__ void cp16s(uint32_t dst, const void* g) {
    asm volatile("cp.async.ca.shared.global [%0], [%1], 16;" :: "r"(dst), "l"(g));
}
__device__ __forceinline__ void cp_commit() {
    asm volatile("cp.async.commit_group;" ::: "memory");
}
__device__ __forceinline__ uint32_t packh2(float x, float y) {
    __half2 h = __floats2half2_rn(x, y);
    return *(uint32_t*)&h;
}
// fp16x2 exp2 (one MUFU issue for two values)
__device__ __forceinline__ uint32_t h2ex2(uint32_t a) {
    uint32_t c; asm("ex2.approx.f16x2 %0, %1;" : "=r"(c) : "r"(a)); return c;
}
__device__ __forceinline__ uint32_t h2add(uint32_t a, uint32_t b) {
    uint32_t c; asm("add.f16x2 %0, %1, %2;" : "=r"(c) : "r"(a), "r"(b)); return c;
}

// ---------------- fused converter --------------------------------------------
__global__ void conv_all(
    const float* __restrict__ wq, const float* __restrict__ wk,
    const float* __restrict__ wv, const float* __restrict__ wo,
    __half* __restrict__ wh,
    const float4* __restrict__ x, __half2* __restrict__ xh)
{
    const int z = blockIdx.z;
    if (z < 4) {
        __shared__ float tle[32][33];
        const float* in = (z == 0) ? wq : (z == 1) ? wk : (z == 2) ? wv : wo;
        __half* o = wh + (size_t)z * DM * DM;
        int bx = blockIdx.x * 32, by = blockIdx.y * 32;
        int tx = threadIdx.x, ty = threadIdx.y;
        #pragma unroll
        for (int i = 0; i < 4; i++)
            tle[ty + 8 * i][tx] = in[(size_t)(by + ty + 8 * i) * DM + bx + tx];
        __syncthreads();
        #pragma unroll
        for (int i = 0; i < 4; i++)
            o[(size_t)(bx + ty + 8 * i) * DM + by + tx] =
                __float2half_rn(tle[tx][ty + 8 * i]);
    } else {
        int tid = threadIdx.y * 32 + threadIdx.x;
        int i = (((z - 4) * 1024 + blockIdx.y * 32 + blockIdx.x) << 8) + tid;
        float4 v = x[i];
        xh[2 * i]     = __floats2half2_rn(v.x, v.y);
        xh[2 * i + 1] = __floats2half2_rn(v.z, v.w);
    }
}

// ============================================================================
// fp16 GEMM core. BM=BN=128, BK=32, 4-stage cp.async, ONE sync per k-tile.
// 4 warps (2m x 2n), warp tile 64x64, B fragments register-double-buffered.
// ============================================================================
#define G_LD   40
#define G_STG  (128 * G_LD)
#define G_NSTG 4
#define G_SMEM (G_NSTG * 2 * G_STG * 2)    // 81920 B

struct GemmAcc { float a[4][8][4]; };

__device__ __forceinline__ void gemm_core(
    const __half* __restrict__ A, const __half* __restrict__ Bt,
    int row0, int col0, GemmAcc& acc, __half* gsm)
{
    const int tid = threadIdx.x;
    const int lane = tid & 31, wid = tid >> 5;
    const int wm = wid & 1, wn = wid >> 1;

    uint32_t sA = (uint32_t)__cvta_generic_to_shared(gsm);
    uint32_t sB = sA + G_NSTG * G_STG * 2;

    const int a_row = (lane & 7) + ((lane >> 3) & 1) * 8;
    const int a_kof = ((lane >> 4) & 1) * 8;
    const int b_row = (lane & 7) + ((lane >> 4) & 1) * 8;
    const int b_kof = ((lane >> 3) & 1) * 8;

    #pragma unroll
    for (int mt = 0; mt < 4; mt++)
        #pragma unroll
        for (int nt = 0; nt < 8; nt++)
            #pragma unroll
            for (int r = 0; r < 4; r++) acc.a[mt][nt][r] = 0.f;

    const int NT = DM / 32;   // 32
    auto issue = [&](int t) {
        if (t < NT) {
            int buf = t % G_NSTG, k0 = t * 32;
            #pragma unroll
            for (int i = 0; i < 4; i++) {
                int idx = tid + i * 128;
                int r = idx >> 2, c = idx & 3;
                uint32_t off = (uint32_t)(buf * G_STG + r * G_LD + c * 8) * 2;
                cp16s(sA + off, A  + (size_t)(row0 + r) * DM + k0 + c * 8);
                cp16s(sB + off, Bt + (size_t)(col0 + r) * DM + k0 + c * 8);
            }
        }
        cp_commit();
    };

    issue(0); issue(1); issue(2);

    for (int it = 0; it < NT; ++it) {
        asm volatile("cp.async.wait_group 2;" ::: "memory");
        __syncthreads();
        issue(it + 3);

        uint32_t ab = sA + (uint32_t)((it % G_NSTG) * G_STG) * 2;
        uint32_t bb = sB + (uint32_t)((it % G_NSTG) * G_STG) * 2;

        uint32_t a[2][4][4];
        #pragma unroll
        for (int ks = 0; ks < 2; ks++)
            #pragma unroll
            for (int mt = 0; mt < 4; mt++)
                ldm4(a[ks][mt], ab + (uint32_t)((wm * 64 + mt * 16 + a_row) * G_LD
                                                + ks * 16 + a_kof) * 2);

        uint32_t bf[2][4];
        ldm4(bf[0], bb + (uint32_t)((wn * 64 + b_row) * G_LD + b_kof) * 2);
        #pragma unroll
        for (int i = 0; i < 8; i++) {
            int ks = i >> 2, ntp = i & 3;
            if (i + 1 < 8) {
                int nks = (i + 1) >> 2, nntp = (i + 1) & 3;
                ldm4(bf[(i + 1) & 1],
                     bb + (uint32_t)((wn * 64 + nntp * 16 + b_row) * G_LD
                                     + nks * 16 + b_kof) * 2);
            }
            const uint32_t* f = bf[i & 1];
            #pragma unroll
            for (int mt = 0; mt < 4; mt++) {
                mma_f16(acc.a[mt][2 * ntp],     a[ks][mt], f[0], f[1]);
                mma_f16(acc.a[mt][2 * ntp + 1], a[ks][mt], f[2], f[3]);
            }
        }
    }
}

// Fused QKV: grid (24, 32). mat = bx>>3 selects weight + destination.
__global__ __launch_bounds__(128, 2) void gemm_qkv(
    const __half* __restrict__ A, const __half* __restrict__ W,
    __half* __restrict__ Qh, __half* __restrict__ Kh, __half* __restrict__ Vh)
{
    extern __shared__ __align__(16) __half gsm[];
    const int mat = blockIdx.x >> 3;
    const int col0 = (blockIdx.x & 7) * 128;
    const int row0 = blockIdx.y * 128;
    const __half* Bt = W + (size_t)mat * DM * DM;
    __half* C = (mat == 0) ? Qh : (mat == 1) ? Kh : Vh;
    const float sc = (mat == 0) ? QSCALE : 1.f;

    GemmAcc acc;
    gemm_core(A, Bt, row0, col0, acc, gsm);

    const int lane = threadIdx.x & 31, wid = threadIdx.x >> 5;
    const int lr = lane >> 2, lc = lane & 3;
    const int wm = wid & 1, wn = wid >> 1;
    #pragma unroll
    for (int mt = 0; mt < 4; mt++) {
        int r = row0 + wm * 64 + mt * 16 + lr;
        #pragma unroll
        for (int nt = 0; nt < 8; nt++) {
            int c = col0 + wn * 64 + nt * 8 + 2 * lc;
            *(__half2*)&C[(size_t)r * DM + c] =
                __floats2half2_rn(acc.a[mt][nt][0] * sc, acc.a[mt][nt][1] * sc);
            *(__half2*)&C[(size_t)(r + 8) * DM + c] =
                __floats2half2_rn(acc.a[mt][nt][2] * sc, acc.a[mt][nt][3] * sc);
        }
    }
}

// Out projection: fp32 output + bias
__global__ __launch_bounds__(128, 2) void gemm_out(
    const __half* __restrict__ A, const __half* __restrict__ Bt,
    const float* __restrict__ bias, float* __restrict__ Cf)
{
    extern __shared__ __align__(16) __half gsm[];
    const int col0 = blockIdx.x * 128, row0 = blockIdx.y * 128;

    GemmAcc acc;
    gemm_core(A, Bt, row0, col0, acc, gsm);

    const int lane = threadIdx.x & 31, wid = threadIdx.x >> 5;
    const int lr = lane >> 2, lc = lane & 3;
    const int wm = wid & 1, wn = wid >> 1;
    #pragma unroll
    for (int mt = 0; mt < 4; mt++) {
        int r = row0 + wm * 64 + mt * 16 + lr;
        #pragma unroll
        for (int nt = 0; nt < 8; nt++) {
            int c = col0 + wn * 64 + nt * 8 + 2 * lc;
            float bx = bias[c], by = bias[c + 1];
            *(float2*)&Cf[(size_t)r * DM + c] =
                make_float2(acc.a[mt][nt][0] + bx, acc.a[mt][nt][1] + by);
            *(float2*)&Cf[(size_t)(r + 8) * DM + c] =
                make_float2(acc.a[mt][nt][2] + bx, acc.a[mt][nt][3] + by);
        }
    }
}

// ============================================================================
// fp16 flash attention (causal, exp2 domain, no max tracking).
// P computed via ex2.approx.f16x2 directly in A-fragment form (half the MUFU
// ops, no separate pack pass); l via f16x2 add-tree + fp32 accumulate.
// 128 q/CTA, 64 kv/tile, 4 warps x 32 q-rows, 2 CTA/SM.
// ============================================================================
#define F_LD   72
#define F_QP   (128 * F_LD)
#define F_KV   (64 * F_LD)
#define F_SMEM ((F_QP + 3 * F_KV + 3 * F_KV) * 2)   // 73728 B

__global__ __launch_bounds__(128, 2) void flash_h(
    const __half* __restrict__ Q, const __half* __restrict__ K,
    const __half* __restrict__ V, __half* __restrict__ O)
{
    extern __shared__ __align__(16) __half fsm[];
    const int tid = threadIdx.x;
    const int lane = tid & 31, wid = tid >> 5;
    const int lr = lane >> 2, lc = lane & 3;
    const int q0 = (gridDim.x - 1 - blockIdx.x) * 128;   // heavy tiles first
    const int h = blockIdx.y, b = blockIdx.z;

    const __half* Qg = Q + (size_t)(b * CTX) * DM + h * HD;
    const __half* Kg = K + (size_t)(b * CTX) * DM + h * HD;
    const __half* Vg = V + (size_t)(b * CTX) * DM + h * HD;

    uint32_t sQ = (uint32_t)__cvta_generic_to_shared(fsm);
    uint32_t sK = sQ + F_QP * 2;
    uint32_t sV = sK + 3 * F_KV * 2;

    const int a_row = (lane & 7) + ((lane >> 3) & 1) * 8;
    const int a_kof = ((lane >> 4) & 1) * 8;
    const int b_row = (lane & 7) + ((lane >> 4) & 1) * 8;
    const int b_kof = ((lane >> 3) & 1) * 8;

    const int nkv = q0 / 64 + 2;

    auto issueKV = [&](int t) {
        if (t < nkv) {
            int kb = t * 64, buf = t % 3;
            #pragma unroll
            for (int i = 0; i < 8; i++) {
                int idx = tid + i * 128;
                int sel = idx >> 9;
                int kk = (idx >> 3) & 63, c = idx & 7;
                const __half* src = (sel ? Vg : Kg) + (size_t)(kb + kk) * DM + c * 8;
                uint32_t dst = (sel ? sV : sK) +
                               (uint32_t)(buf * F_KV + kk * F_LD + c * 8) * 2;
                cp16s(dst, src);
            }
        }
        cp_commit();
    };

    // prologue: Q tile joins tile-0's commit group
    #pragma unroll
    for (int i = 0; i < 8; i++) {
        int idx = tid + i * 128;
        int q = idx >> 3, c = idx & 7;
        cp16s(sQ + (uint32_t)(q * F_LD + c * 8) * 2, Qg + (size_t)(q0 + q) * DM + c * 8);
    }
    issueKV(0);
    issueKV(1);

    const int qw = wid * 32;
    const int vrow = lane & 15;
    const int vblk = lane >> 4;

    // ---- hoist Q fragments ----
    asm volatile("cp.async.wait_group 1;" ::: "memory");
    __syncthreads();
    uint32_t qa[4][2][4];
    #pragma unroll
    for (int ks = 0; ks < 4; ks++)
        #pragma unroll
        for (int mt = 0; mt < 2; mt++)
            ldm4(qa[ks][mt], sQ + (uint32_t)((qw + mt * 16 + a_row) * F_LD
                                             + ks * 16 + a_kof) * 2);

    float l0[2] = {0.f, 0.f}, l1[2] = {0.f, 0.f};
    float o[2][8][4];
    #pragma unroll
    for (int mt = 0; mt < 2; mt++)
        #pragma unroll
        for (int dt = 0; dt < 8; dt++)
            #pragma unroll
            for (int r = 0; r < 4; r++) o[mt][dt][r] = 0.f;

    for (int t = 0; t < nkv; ++t) {
        asm volatile("cp.async.wait_group 1;" ::: "memory");
        __syncthreads();

        uint32_t kbuf = sK + (uint32_t)((t % 3) * F_KV) * 2;
        uint32_t vbuf = sV + (uint32_t)((t % 3) * F_KV) * 2;

        // ---- S = Q @ K^T: K fragments pipelined over 16 (ks,ntp) steps ----
        float s[2][8][4];
        #pragma unroll
        for (int mt = 0; mt < 2; mt++)
            #pragma unroll
            for (int nt = 0; nt < 8; nt++)
                #pragma unroll
                for (int r = 0; r < 4; r++) s[mt][nt][r] = 0.f;

        {
            uint32_t bf[2][4];
            ldm4(bf[0], kbuf + (uint32_t)(b_row * F_LD + b_kof) * 2);
            #pragma unroll
            for (int i = 0; i < 16; i++) {
                int ks = i >> 2, ntp = i & 3;
                if (i + 1 < 16) {
                    int nks = (i + 1) >> 2, nntp = (i + 1) & 3;
                    ldm4(bf[(i + 1) & 1],
                         kbuf + (uint32_t)((nntp * 16 + b_row) * F_LD
                                           + nks * 16 + b_kof) * 2);
                }
                const uint32_t* f = bf[i & 1];
                #pragma unroll
                for (int mt = 0; mt < 2; mt++) {
                    mma_f16(s[mt][2 * ntp],     qa[ks][mt], f[0], f[1]);
                    mma_f16(s[mt][2 * ntp + 1], qa[ks][mt], f[2], f[3]);
                }
            }
        }

        issueKV(t + 2);   // buffer consumed at t-1; sync above proves safety

        const int kb = t * 64;

        if (kb + 63 > q0) {
            #pragma unroll
            for (int mt = 0; mt < 2; mt++) {
                int r0 = q0 + qw + mt * 16 + lr, r1 = r0 + 8;
                #pragma unroll
                for (int nt = 0; nt < 8; nt++) {
                    #pragma unroll
                    for (int j = 0; j < 2; j++) {
                        int key = kb + nt * 8 + 2 * lc + j;
                        if (key > r0) s[mt][nt][j]     = -1e30f;
                        if (key > r1) s[mt][nt][2 + j] = -1e30f;
                    }
                }
            }
        }

        // ---- P = exp2(S) in fp16x2, directly in A-fragment layout ----
        // pa[ks][mt][0,2]: row r0 (cols 2ks, 2ks+1); pa[ks][mt][1,3]: row r1.
        uint32_t pa[4][2][4];
        #pragma unroll
        for (int ks = 0; ks < 4; ks++)
            #pragma unroll
            for (int mt = 0; mt < 2; mt++) {
                pa[ks][mt][0] = h2ex2(packh2(s[mt][2 * ks][0],     s[mt][2 * ks][1]));
                pa[ks][mt][1] = h2ex2(packh2(s[mt][2 * ks][2],     s[mt][2 * ks][3]));
                pa[ks][mt][2] = h2ex2(packh2(s[mt][2 * ks + 1][0], s[mt][2 * ks + 1][1]));
                pa[ks][mt][3] = h2ex2(packh2(s[mt][2 * ks + 1][2], s[mt][2 * ks + 1][3]));
            }

        // ---- l += rowsum(P): f16x2 tree (7 adds/row) + fp32 finish ----
        #pragma unroll
        for (int mt = 0; mt < 2; mt++) {
            uint32_t u0 = h2add(h2add(h2add(pa[0][mt][0], pa[0][mt][2]),
                                      h2add(pa[1][mt][0], pa[1][mt][2])),
                                h2add(h2add(pa[2][mt][0], pa[2][mt][2]),
                                      h2add(pa[3][mt][0], pa[3][mt][2])));
            uint32_t u1 = h2add(h2add(h2add(pa[0][mt][1], pa[0][mt][3]),
                                      h2add(pa[1][mt][1], pa[1][mt][3])),
                                h2add(h2add(pa[2][mt][1], pa[2][mt][3]),
                                      h2add(pa[3][mt][1], pa[3][mt][3])));
            float2 f0 = __half22float2(*(__half2*)&u0);
            float2 f1 = __half22float2(*(__half2*)&u1);
            l0[mt] += f0.x + f0.y;
            l1[mt] += f1.x + f1.y;
        }

        // ---- O += P @ V: V fragments pipelined over 16 (ks,ntp) steps ----
        {
            uint32_t vb[2][4];
            ldm4t(vb[0], vbuf + (uint32_t)(vrow * F_LD + vblk * 8) * 2);
            #pragma unroll
            for (int i = 0; i < 16; i++) {
                int ks = i >> 2, ntp = i & 3;
                if (i + 1 < 16) {
                    int nks = (i + 1) >> 2, nntp = (i + 1) & 3;
                    ldm4t(vb[(i + 1) & 1],
                          vbuf + (uint32_t)((nks * 16 + vrow) * F_LD
                                            + (2 * nntp + vblk) * 8) * 2);
                }
                const uint32_t* f = vb[i & 1];
                #pragma unroll
                for (int mt = 0; mt < 2; mt++) {
                    mma_f16(o[mt][2 * ntp],     pa[ks][mt], f[0], f[1]);
                    mma_f16(o[mt][2 * ntp + 1], pa[ks][mt], f[2], f[3]);
                }
            }
        }
    }

    // ---- epilogue: reduce l across the quad (once), normalize, write ----
    __half* Og = O + (size_t)(b * CTX) * DM + h * HD;
    #pragma unroll
    for (int mt = 0; mt < 2; mt++) {
        float r0sum = l0[mt], r1sum = l1[mt];
        r0sum += __shfl_xor_sync(0xffffffffu, r0sum, 1);
        r0sum += __shfl_xor_sync(0xffffffffu, r0sum, 2);
        r1sum += __shfl_xor_sync(0xffffffffu, r1sum, 1);
        r1sum += __shfl_xor_sync(0xffffffffu, r1sum, 2);
        float i0 = 1.f / r0sum, i1 = 1.f / r1sum;
        int r0 = q0 + qw + mt * 16 + lr;
        #pragma unroll
        for (int dt = 0; dt < 8; dt++) {
            int c = dt * 8 + 2 * lc;
            *(__half2*)&Og[(size_t)r0 * DM + c] =
                __floats2half2_rn(o[mt][dt][0] * i0, o[mt][dt][1] * i0);
            *(__half2*)&Og[(size_t)(r0 + 8) * DM + c] =
                __floats2half2_rn(o[mt][dt][2] * i1, o[mt][dt][3] * i1);
        }
    }
}

// ============================================================================
// launch
// ============================================================================
extern "C" void kernel_launch(void* const* d_in, const int* in_sizes, int n_in,
                              void* d_out, int out_size)
{
    const float* x  = (const float*)d_in[0];
    const float* Wq = (const float*)d_in[1];
    const float* Wk = (const float*)d_in[2];
    const float* Wv = (const float*)d_in[3];
    const float* Wo = (const float*)d_in[4];
    const float* bo = (const float*)d_in[5];
    float* out = (float*)d_out;

    __half *Xh, *Wh, *Qh, *Kh, *Vh, *Ch;
    cudaGetSymbolAddress((void**)&Xh, g_Xh);
    cudaGetSymbolAddress((void**)&Wh, g_Wh);
    cudaGetSymbolAddress((void**)&Qh, g_Qh);
    cudaGetSymbolAddress((void**)&Kh, g_Kh);
    cudaGetSymbolAddress((void**)&Vh, g_Vh);
    cudaGetSymbolAddress((void**)&Ch, g_Ch);

    cudaFuncSetAttribute(gemm_qkv, cudaFuncAttributeMaxDynamicSharedMemorySize, G_SMEM);
    cudaFuncSetAttribute(gemm_out, cudaFuncAttributeMaxDynamicSharedMemorySize, G_SMEM);
    cudaFuncSetAttribute(flash_h, cudaFuncAttributeMaxDynamicSharedMemorySize, F_SMEM);

    // fused converters: weights (z<4) + x (z>=4)
    dim3 cgrid(32, 32, 8), cblk(32, 8);
    conv_all<<<cgrid, cblk>>>(Wq, Wk, Wv, Wo, Wh, (const float4*)x, (__half2*)Xh);

    dim3 qgrid(24, BT / 128);          // fused QKV
    gemm_qkv<<<qgrid, 128, G_SMEM>>>(Xh, Wh, Qh, Kh, Vh);

    dim3 fgrid(CTX / 128, NH, BATCH);  // (16, 16, 2)
    flash_h<<<fgrid, 128, F_SMEM>>>(Qh, Kh, Vh, Ch);

    dim3 ogrid(DM / 128, BT / 128);
    gemm_out<<<ogrid, 128, G_SMEM>>>(Ch, Wh + 3 * (size_t)DM * DM, bo, out);
}